// round 1
// baseline (speedup 1.0000x reference)
#include <cuda_runtime.h>
#include <cstdint>

// ---------------- problem constants ----------------
static constexpr int NIMG = 8192;      // B*N
static constexpr int PIX  = 81;        // 9x9
static constexpr int BATCH = 64;
static constexpr int NAGENT = 128;
static constexpr int ENCF = 128;
static constexpr int KDIM = 10368;     // 128*81
static constexpr float BN_EPS = 1e-5f;
static constexpr float INV_CNT = 1.0f / (8192.0f * 81.0f);  // BN count = NIMG*PIX

// ---------------- device scratch (no cudaMalloc allowed) ----------------
__device__ float d_conv1[NIMG * 32 * PIX];
__device__ float d_conv2[NIMG * 64 * PIX];
__device__ float d_conv3[NIMG * 128 * PIX];
__device__ float d_part[2 * NIMG * ENCF];
__device__ float d_xcat1[BATCH * 384 * NAGENT];
__device__ float d_xcat2[BATCH * 384 * NAGENT];
__device__ float d_xg2[BATCH * 128 * NAGENT];
__device__ float d_gsum[384];
__device__ float d_gsq[384];
__device__ float d_bnA[128];
__device__ float d_bnB[128];

// ---------------- fused conv + bias + BN-stats ----------------
// block: (TASKS, IPB). One image per ty slice. Each thread: one output row (9 px)
// for CG consecutive output channels. Input zero-padded 11x11 in smem, weights in
// smem with odd row stride for bank-conflict-free loads.
template <int CIN, int COUT_T, int CG, int IPB>
__global__ void conv_bn_stats_kernel(const float* __restrict__ gin,
                                     const float* __restrict__ gw,
                                     const float* __restrict__ gbias,
                                     float* __restrict__ gout,
                                     float* __restrict__ gsum,
                                     float* __restrict__ gsq,
                                     int cout_total) {
    constexpr int TASKS = (COUT_T / CG) * 9;
    constexpr int WROW = CIN * 9;
    constexpr int WSTR = (WROW % 2 == 0) ? (WROW + 1) : (WROW + 2);
    extern __shared__ float sm[];
    float* w_s  = sm;                        // COUT_T * WSTR
    float* in_s = w_s + COUT_T * WSTR;       // IPB * CIN * 121
    float* red  = in_s + IPB * CIN * 121;    // 2 * COUT_T

    const int tx = threadIdx.x;
    const int ty = threadIdx.y;
    const int tid = ty * TASKS + tx;
    const int nthr = TASKS * IPB;
    const int img = blockIdx.x * IPB + ty;
    const int co_base = blockIdx.y * COUT_T;

    // weights -> smem
    for (int idx = tid; idx < COUT_T * WROW; idx += nthr) {
        int co = idx / WROW, r = idx - co * WROW;
        w_s[co * WSTR + r] = gw[(co_base + co) * WROW + r];
    }
    for (int idx = tid; idx < 2 * COUT_T; idx += nthr) red[idx] = 0.f;
    for (int idx = tid; idx < IPB * CIN * 121; idx += nthr) in_s[idx] = 0.f;
    __syncthreads();
    {
        const float* ip = gin + (long long)img * (CIN * 81);
        float* is = in_s + ty * (CIN * 121);
        for (int idx = tx; idx < CIN * 81; idx += TASKS) {
            int ch = idx / 81, p = idx - ch * 81;
            int y = p / 9, x = p - y * 9;
            is[ch * 121 + (y + 1) * 11 + (x + 1)] = ip[idx];
        }
    }
    __syncthreads();

    const int grp = tx / 9;
    const int y = tx - grp * 9;
    float acc[CG][9];
#pragma unroll
    for (int j = 0; j < CG; j++)
#pragma unroll
        for (int x = 0; x < 9; x++) acc[j][x] = 0.f;

    const float* is = in_s + ty * (CIN * 121);
    for (int ci = 0; ci < CIN; ci++) {
        float r0[11], r1[11], r2[11];
        const float* rp = is + ci * 121 + y * 11;
#pragma unroll
        for (int x = 0; x < 11; x++) { r0[x] = rp[x]; r1[x] = rp[11 + x]; r2[x] = rp[22 + x]; }
#pragma unroll
        for (int j = 0; j < CG; j++) {
            const float* wp = w_s + (grp * CG + j) * WSTR + ci * 9;
            float w0 = wp[0], w1 = wp[1], w2 = wp[2];
            float w3 = wp[3], w4 = wp[4], w5 = wp[5];
            float w6 = wp[6], w7 = wp[7], w8 = wp[8];
#pragma unroll
            for (int x = 0; x < 9; x++) {
                float s = acc[j][x];
                s += r0[x] * w0; s += r0[x + 1] * w1; s += r0[x + 2] * w2;
                s += r1[x] * w3; s += r1[x + 1] * w4; s += r1[x + 2] * w5;
                s += r2[x] * w6; s += r2[x + 1] * w7; s += r2[x + 2] * w8;
                acc[j][x] = s;
            }
        }
    }

#pragma unroll
    for (int j = 0; j < CG; j++) {
        int co = co_base + grp * CG + j;
        float b = gbias[co];
        float* op = gout + ((long long)img * cout_total + co) * 81 + y * 9;
        float s = 0.f, ss = 0.f;
#pragma unroll
        for (int x = 0; x < 9; x++) {
            float v = acc[j][x] + b;
            op[x] = v;
            s += v;
            ss += v * v;
        }
        atomicAdd(&red[grp * CG + j], s);
        atomicAdd(&red[COUT_T + grp * CG + j], ss);
    }
    __syncthreads();
    for (int idx = tid; idx < COUT_T; idx += nthr) {
        atomicAdd(&gsum[co_base + idx], red[idx]);
        atomicAdd(&gsq[co_base + idx], red[COUT_T + idx]);
    }
}

// ---------------- BN helpers ----------------
__global__ void zero_stats_kernel(float* gsum, float* gsq) {
    int t = threadIdx.x;
    if (t < 384) { gsum[t] = 0.f; gsq[t] = 0.f; }
}

__global__ void bn_prep_kernel(const float* gsum, const float* gsq,
                               const float* gamma, const float* beta,
                               float* a, float* b, int C) {
    int c = threadIdx.x;
    if (c < C) {
        float mu = gsum[c] * INV_CNT;
        float var = gsq[c] * INV_CNT - mu * mu;
        float ai = gamma[c] * rsqrtf(var + BN_EPS);
        a[c] = ai;
        b[c] = beta[c] - mu * ai;
    }
}

__global__ void bn_relu_kernel(float* __restrict__ x, const float* __restrict__ a,
                               const float* __restrict__ b, int C, int total4) {
    int i = blockIdx.x * blockDim.x + threadIdx.x;
    if (i >= total4) return;
    float4 v = reinterpret_cast<float4*>(x)[i];
    long long base = (long long)i * 4;
    int c0 = (int)((base) / 81) % C;
    int c1 = (int)((base + 1) / 81) % C;
    int c2 = (int)((base + 2) / 81) % C;
    int c3 = (int)((base + 3) / 81) % C;
    v.x = fmaxf(fmaf(a[c0], v.x, b[c0]), 0.f);
    v.y = fmaxf(fmaf(a[c1], v.y, b[c1]), 0.f);
    v.z = fmaxf(fmaf(a[c2], v.z, b[c2]), 0.f);
    v.w = fmaxf(fmaf(a[c3], v.w, b[c3]), 0.f);
    reinterpret_cast<float4*>(x)[i] = v;
}

// ---------------- encoder GEMM: C[m][e] = sum_k A[m][k] * W[e][k], split-K=2 ----------------
__global__ void gemm_enc_kernel(const float* __restrict__ A, const float* __restrict__ W,
                                float* __restrict__ part) {
    __shared__ float As[64][17];
    __shared__ float Ws[128][17];
    const int tx = threadIdx.x;
    const int mb = blockIdx.x * 64;
    const int ks = blockIdx.z;
    const int k0 = ks * 5184;

    float acc[8][4];
#pragma unroll
    for (int i = 0; i < 8; i++)
#pragma unroll
        for (int j = 0; j < 4; j++) acc[i][j] = 0.f;

    const int mi = tx >> 5;  // 0..7
    const int ej = tx & 31;  // 0..31

    for (int t = 0; t < 324; t++) {
        int kb = k0 + t * 16;
#pragma unroll
        for (int l = 0; l < 4; l++) {
            int idx = tx + l * 256;
            int r = idx >> 4, c = idx & 15;
            As[r][c] = A[(long long)(mb + r) * KDIM + kb + c];
        }
#pragma unroll
        for (int l = 0; l < 8; l++) {
            int idx = tx + l * 256;
            int r = idx >> 4, c = idx & 15;
            Ws[r][c] = W[(long long)r * KDIM + kb + c];
        }
        __syncthreads();
#pragma unroll
        for (int k = 0; k < 16; k++) {
            float av[8], wv[4];
#pragma unroll
            for (int i = 0; i < 8; i++) av[i] = As[mi + 8 * i][k];
#pragma unroll
            for (int j = 0; j < 4; j++) wv[j] = Ws[ej + 32 * j][k];
#pragma unroll
            for (int i = 0; i < 8; i++)
#pragma unroll
                for (int j = 0; j < 4; j++) acc[i][j] = fmaf(av[i], wv[j], acc[i][j]);
        }
        __syncthreads();
    }
#pragma unroll
    for (int i = 0; i < 8; i++)
#pragma unroll
        for (int j = 0; j < 4; j++)
            part[ks * (NIMG * ENCF) + (mb + mi + 8 * i) * ENCF + (ej + 32 * j)] = acc[i][j];
}

// combine split-K partials + bias, write transposed into xcat rows [0:128)
__global__ void combine_enc_kernel(const float* __restrict__ part, const float* __restrict__ enc_b,
                                   float* __restrict__ xcat) {
    int idx = blockIdx.x * 256 + threadIdx.x;  // < 1048576
    int e = idx & 127;
    int m = idx >> 7;
    int b = m >> 7;
    int n = m & 127;
    float v = part[idx] + part[NIMG * ENCF + idx] + enc_b[e];
    xcat[b * (384 * 128) + e * 128 + n] = v;
}

// ---------------- batched X*S and X*S^2, filling rows [128:256) and [256:384) ----------------
__global__ void xs_kernel(float* __restrict__ xcat, const float* __restrict__ gso) {
    extern __shared__ float sm[];
    float (*Xs)[129] = (float (*)[129])sm;
    float (*Ss)[129] = (float (*)[129])(sm + 128 * 129);
    const int b = blockIdx.x, tx = threadIdx.x;

    for (int l = 0; l < 64; l++) {
        int idx = tx + l * 256;
        int r = idx >> 7, c = idx & 127;
        Ss[r][c] = gso[b * 16384 + idx];
        Xs[r][c] = xcat[b * (384 * 128) + idx];
    }
    __syncthreads();

    const int nj = tx & 15;   // m = nj + 16*j
    const int fi = tx >> 4;   // f = fi + 16*i
    float acc[8][8];

    for (int pass = 0; pass < 2; pass++) {
#pragma unroll
        for (int i = 0; i < 8; i++)
#pragma unroll
            for (int j = 0; j < 8; j++) acc[i][j] = 0.f;
        for (int n = 0; n < 128; n++) {
            float xv[8], sv[8];
#pragma unroll
            for (int i = 0; i < 8; i++) xv[i] = Xs[fi + 16 * i][n];
#pragma unroll
            for (int j = 0; j < 8; j++) sv[j] = Ss[n][nj + 16 * j];
#pragma unroll
            for (int i = 0; i < 8; i++)
#pragma unroll
                for (int j = 0; j < 8; j++) acc[i][j] = fmaf(xv[i], sv[j], acc[i][j]);
        }
        __syncthreads();
        float* gdst = xcat + b * (384 * 128) + (pass + 1) * 16384;
#pragma unroll
        for (int i = 0; i < 8; i++)
#pragma unroll
            for (int j = 0; j < 8; j++) {
                float v = acc[i][j];
                Xs[fi + 16 * i][nj + 16 * j] = v;
                gdst[(fi + 16 * i) * 128 + (nj + 16 * j)] = v;
            }
        __syncthreads();
    }
}

// ---------------- graph-filter GEMM: y[b] = relu(Wcat(128x384) * xcat[b](384x128) + bias) ----------------
__global__ void gfilter_kernel(const float* __restrict__ xcat, const float* __restrict__ W,
                               const float* __restrict__ bias, float* __restrict__ out,
                               int out_stride) {
    extern __shared__ float sm[];
    float (*Ws)[97] = (float (*)[97])sm;                 // [128][97]
    float (*Xs)[129] = (float (*)[129])(sm + 128 * 97);  // [96][129]
    const int b = blockIdx.x, tx = threadIdx.x;
    const int nj = tx & 15;   // n = nj + 16*j
    const int gi = tx >> 4;   // g = gi + 16*i

    float acc[8][8];
#pragma unroll
    for (int i = 0; i < 8; i++)
#pragma unroll
        for (int j = 0; j < 8; j++) acc[i][j] = 0.f;

    for (int kt = 0; kt < 4; kt++) {
        for (int l = 0; l < 48; l++) {
            int idx = tx + l * 256;  // < 12288
            int g = idx / 96, kc = idx - g * 96;
            int kg = kt * 96 + kc;
            Ws[g][kc] = W[(kg >> 7) * 16384 + g * 128 + (kg & 127)];
        }
        for (int l = 0; l < 48; l++) {
            int idx = tx + l * 256;
            int r = idx >> 7, c = idx & 127;
            Xs[r][c] = xcat[b * (384 * 128) + (kt * 96 + r) * 128 + c];
        }
        __syncthreads();
        for (int kc = 0; kc < 96; kc++) {
            float xv[8], wv[8];
#pragma unroll
            for (int j = 0; j < 8; j++) xv[j] = Xs[kc][nj + 16 * j];
#pragma unroll
            for (int i = 0; i < 8; i++) wv[i] = Ws[gi + 16 * i][kc];
#pragma unroll
            for (int i = 0; i < 8; i++)
#pragma unroll
                for (int j = 0; j < 8; j++) acc[i][j] = fmaf(wv[i], xv[j], acc[i][j]);
        }
        __syncthreads();
    }
#pragma unroll
    for (int i = 0; i < 8; i++) {
        int g = gi + 16 * i;
        float bb = bias[g];
#pragma unroll
        for (int j = 0; j < 8; j++) {
            int n = nj + 16 * j;
            out[b * out_stride + g * 128 + n] = fmaxf(acc[i][j] + bb, 0.f);
        }
    }
}

// ---------------- action head ----------------
__global__ void act_kernel(const float* __restrict__ xg2, const float* __restrict__ aw,
                           const float* __restrict__ ab, float* __restrict__ out) {
    int idx = blockIdx.x * 256 + threadIdx.x;  // 40960 total
    int a = idx % 5;
    int n = (idx / 5) & 127;
    int b = idx / 640;
    const float* xp = xg2 + b * 16384 + n;
    const float* wp = aw + a * 128;
    float s = ab[a];
#pragma unroll 8
    for (int g = 0; g < 128; g++) s = fmaf(xp[g * 128], wp[g], s);
    out[idx] = s;
}

// ---------------- host launcher ----------------
extern "C" void kernel_launch(void* const* d_in, const int* in_sizes, int n_in,
                              void* d_out, int out_size) {
    (void)in_sizes; (void)n_in; (void)out_size;
    const float* states = (const float*)d_in[0];
    const float* gso    = (const float*)d_in[1];
    const float* c1_w = (const float*)d_in[2];
    const float* c1_b = (const float*)d_in[3];
    const float* c1_g = (const float*)d_in[4];
    const float* c1_be = (const float*)d_in[5];
    const float* c2_w = (const float*)d_in[6];
    const float* c2_b = (const float*)d_in[7];
    const float* c2_g = (const float*)d_in[8];
    const float* c2_be = (const float*)d_in[9];
    const float* c3_w = (const float*)d_in[10];
    const float* c3_b = (const float*)d_in[11];
    const float* c3_g = (const float*)d_in[12];
    const float* c3_be = (const float*)d_in[13];
    const float* enc_w = (const float*)d_in[14];
    const float* enc_b = (const float*)d_in[15];
    const float* g1_w = (const float*)d_in[16];
    const float* g1_b = (const float*)d_in[17];
    const float* g2_w = (const float*)d_in[18];
    const float* g2_b = (const float*)d_in[19];
    const float* act_w = (const float*)d_in[20];
    const float* act_b = (const float*)d_in[21];
    float* out = (float*)d_out;

    void *p1, *p2, *p3, *ppart, *pxc1, *pxc2, *pxg2, *psum, *psq, *pA, *pB;
    cudaGetSymbolAddress(&p1, d_conv1);
    cudaGetSymbolAddress(&p2, d_conv2);
    cudaGetSymbolAddress(&p3, d_conv3);
    cudaGetSymbolAddress(&ppart, d_part);
    cudaGetSymbolAddress(&pxc1, d_xcat1);
    cudaGetSymbolAddress(&pxc2, d_xcat2);
    cudaGetSymbolAddress(&pxg2, d_xg2);
    cudaGetSymbolAddress(&psum, d_gsum);
    cudaGetSymbolAddress(&psq, d_gsq);
    cudaGetSymbolAddress(&pA, d_bnA);
    cudaGetSymbolAddress(&pB, d_bnB);
    float* conv1 = (float*)p1;
    float* conv2 = (float*)p2;
    float* conv3 = (float*)p3;
    float* part = (float*)ppart;
    float* xcat1 = (float*)pxc1;
    float* xcat2 = (float*)pxc2;
    float* xg2 = (float*)pxg2;
    float* gsum = (float*)psum;
    float* gsq = (float*)psq;
    float* bnA = (float*)pA;
    float* bnB = (float*)pB;

    // dynamic smem sizes (bytes)
    const int SM1 = (32 * 29 + 4 * 3 * 121 + 64) * 4;       // 9776
    const int SM2 = (64 * 289 + 2 * 32 * 121 + 128) * 4;    // 105472
    const int SM3 = (64 * 577 + 2 * 64 * 121 + 128) * 4;    // 210176
    const int XS_SMEM = 2 * 128 * 129 * 4;                  // 132096
    const int GF_SMEM = (128 * 97 + 96 * 129) * 4;          // 99200

    cudaFuncSetAttribute(conv_bn_stats_kernel<3, 32, 4, 4>,
                         cudaFuncAttributeMaxDynamicSharedMemorySize, SM1);
    cudaFuncSetAttribute(conv_bn_stats_kernel<32, 64, 4, 2>,
                         cudaFuncAttributeMaxDynamicSharedMemorySize, SM2);
    cudaFuncSetAttribute(conv_bn_stats_kernel<64, 64, 4, 2>,
                         cudaFuncAttributeMaxDynamicSharedMemorySize, SM3);
    cudaFuncSetAttribute(xs_kernel, cudaFuncAttributeMaxDynamicSharedMemorySize, XS_SMEM);
    cudaFuncSetAttribute(gfilter_kernel, cudaFuncAttributeMaxDynamicSharedMemorySize, GF_SMEM);

    zero_stats_kernel<<<1, 384>>>(gsum, gsq);

    // conv1: 3 -> 32
    conv_bn_stats_kernel<3, 32, 4, 4>
        <<<dim3(NIMG / 4, 1), dim3(72, 4), SM1>>>(states, c1_w, c1_b, conv1, gsum, gsq, 32);
    bn_prep_kernel<<<1, 128>>>(gsum, gsq, c1_g, c1_be, bnA, bnB, 32);
    {
        int total4 = NIMG * 32 * PIX / 4;
        bn_relu_kernel<<<(total4 + 255) / 256, 256>>>(conv1, bnA, bnB, 32, total4);
    }

    // conv2: 32 -> 64
    conv_bn_stats_kernel<32, 64, 4, 2>
        <<<dim3(NIMG / 2, 1), dim3(144, 2), SM2>>>(conv1, c2_w, c2_b, conv2, gsum + 128, gsq + 128, 64);
    bn_prep_kernel<<<1, 128>>>(gsum + 128, gsq + 128, c2_g, c2_be, bnA, bnB, 64);
    {
        int total4 = NIMG * 64 * PIX / 4;
        bn_relu_kernel<<<(total4 + 255) / 256, 256>>>(conv2, bnA, bnB, 64, total4);
    }

    // conv3: 64 -> 128 (two 64-channel tiles)
    conv_bn_stats_kernel<64, 64, 4, 2>
        <<<dim3(NIMG / 2, 2), dim3(144, 2), SM3>>>(conv2, c3_w, c3_b, conv3, gsum + 256, gsq + 256, 128);
    bn_prep_kernel<<<1, 128>>>(gsum + 256, gsq + 256, c3_g, c3_be, bnA, bnB, 128);
    {
        int total4 = NIMG * 128 * PIX / 4;
        bn_relu_kernel<<<(total4 + 255) / 256, 256>>>(conv3, bnA, bnB, 128, total4);
    }

    // encoder GEMM (split-K=2) + combine/transpose into xcat1 rows [0:128)
    gemm_enc_kernel<<<dim3(128, 1, 2), 256>>>(conv3, enc_w, part);
    combine_enc_kernel<<<4096, 256>>>(part, enc_b, xcat1);

    // graph layer 1
    xs_kernel<<<BATCH, 256, XS_SMEM>>>(xcat1, gso);
    gfilter_kernel<<<BATCH, 256, GF_SMEM>>>(xcat1, g1_w, g1_b, xcat2, 384 * 128);

    // graph layer 2
    xs_kernel<<<BATCH, 256, XS_SMEM>>>(xcat2, gso);
    gfilter_kernel<<<BATCH, 256, GF_SMEM>>>(xcat2, g2_w, g2_b, xg2, 128 * 128);

    // action head
    act_kernel<<<160, 256>>>(xg2, act_w, act_b, out);
}